// round 4
// baseline (speedup 1.0000x reference)
#include <cuda_runtime.h>
#include <math.h>

#define BB 8
#define TT 2048
#define DUx 512
#define DMx 512
#define DAx 256
#define DFx 12
#define DXx 516
#define NSTAGE 4
#define EPSV 1e-6f
#define INV_SCALE (1.0f/16.0f)

// ---------------- scratch (device globals; no allocation) ----------------
__device__ float g_usq[BB*TT];
__device__ float g_sbias[BB*TT];
__device__ float g_logits[BB*TT];
__device__ float g_y[BB*TT];
__device__ float g_overlap[BB*TT];
__device__ float g_sp[BB*TT];      // sim @ prev (accumulated)
__device__ float g_yu[BB*DUx];     // y @ u  (raw centroid)
__device__ float g_x[BB*DXx];      // GRU input [z, c]
__device__ float g_memA[BB*DMx];
__device__ float g_memB[BB*DMx];
__device__ float g_qk[BB*DUx];     // Wk^T @ q
__device__ float g_stat[BB*8];     // [ysum_clamped, coverage, entropy, wsq, spread_acc]

// ---------------- reduction helpers ----------------
__device__ __forceinline__ float warpSum(float v){
    #pragma unroll
    for (int o = 16; o; o >>= 1) v += __shfl_xor_sync(0xffffffffu, v, o);
    return v;
}
__device__ __forceinline__ float warpMax(float v){
    #pragma unroll
    for (int o = 16; o; o >>= 1) v = fmaxf(v, __shfl_xor_sync(0xffffffffu, v, o));
    return v;
}
__device__ __forceinline__ float blockSum(float v, float* sh){
    int lane = threadIdx.x & 31, w = threadIdx.x >> 5;
    int nw = (blockDim.x + 31) >> 5;
    v = warpSum(v);
    if (lane == 0) sh[w] = v;
    __syncthreads();
    if (w == 0){
        float x = (lane < nw) ? sh[lane] : 0.f;
        x = warpSum(x);
        if (lane == 0) sh[0] = x;
    }
    __syncthreads();
    float r = sh[0];
    __syncthreads();
    return r;
}
__device__ __forceinline__ float blockMax(float v, float* sh){
    int lane = threadIdx.x & 31, w = threadIdx.x >> 5;
    int nw = (blockDim.x + 31) >> 5;
    v = warpMax(v);
    if (lane == 0) sh[w] = v;
    __syncthreads();
    if (w == 0){
        float x = (lane < nw) ? sh[lane] : -INFINITY;
        x = warpMax(x);
        if (lane == 0) sh[0] = x;
    }
    __syncthreads();
    float r = sh[0];
    __syncthreads();
    return r;
}

// ---------------- init: zero sp, copy memory0 ----------------
__global__ void k_init(const float* __restrict__ mem0){
    int i = blockIdx.x * blockDim.x + threadIdx.x;
    if (i < BB*TT) g_sp[i] = 0.f;
    if (i < BB*DMx) g_memA[i] = mem0[i];
}

// ---------------- precompute: usq[b,t], sbias[b,t] ----------------
__global__ void k_pre(const float* __restrict__ u, const float* __restrict__ sf,
                      const float* __restrict__ w1, const float* __restrict__ b1,
                      const float* __restrict__ w2, const float* __restrict__ b2){
    int b  = blockIdx.x >> 8;
    int t0 = (blockIdx.x & 255) * 8;
    int w = threadIdx.x >> 5, lane = threadIdx.x & 31;
    int t = t0 + w, bt = b*TT + t;
    const float4* up = (const float4*)(u + (size_t)bt * DUx);
    float acc = 0.f;
    #pragma unroll
    for (int c = 0; c < 4; c++){
        float4 a = up[c*32 + lane];
        acc += a.x*a.x + a.y*a.y + a.z*a.z + a.w*a.w;
    }
    acc = warpSum(acc);
    float d0 = sf[bt*DFx + 8], d1 = sf[bt*DFx + 9], d2 = sf[bt*DFx + 10];
    float sb = 0.f;
    #pragma unroll
    for (int k = 0; k < 8; k++){
        int a = lane + k*32;
        float h = w1[a*3+0]*d0 + w1[a*3+1]*d1 + w1[a*3+2]*d2 + b1[a];
        h = 0.5f * h * (1.f + erff(h * 0.70710678118654752f));  // exact GELU
        sb += h * w2[a];
    }
    sb = warpSum(sb);
    if (lane == 0){ g_usq[bt] = acc; g_sbias[bt] = sb + b2[0]; }
}

// ---------------- q = Wq@mem ; qk = Wk^T@q ----------------
__global__ void k_qqk(const float* __restrict__ Wq, const float* __restrict__ Wk, int inB){
    const float* mem_in = inB ? g_memB : g_memA;
    int b = blockIdx.x;
    __shared__ float4 s_m4[DMx/4];
    __shared__ float s_q[DAx];
    float* s_m = (float*)s_m4;
    for (int i = threadIdx.x; i < DMx; i += 256) s_m[i] = mem_in[b*DMx + i];
    __syncthreads();
    int w = threadIdx.x >> 5, lane = threadIdx.x & 31;
    for (int k = 0; k < 32; k++){
        int a = w*32 + k;
        const float4* row = (const float4*)(Wq + (size_t)a * DMx);
        float acc = 0.f;
        #pragma unroll
        for (int cc = 0; cc < 4; cc++){
            float4 r4 = row[cc*32 + lane], m4 = s_m4[cc*32 + lane];
            acc += r4.x*m4.x + r4.y*m4.y + r4.z*m4.z + r4.w*m4.w;
        }
        acc = warpSum(acc);
        if (lane == 0) s_q[a] = acc;
    }
    __syncthreads();
    float a0 = 0.f, a1 = 0.f;
    for (int a = 0; a < DAx; a++){
        float qv = s_q[a];
        a0 += Wk[(size_t)a*DUx + threadIdx.x]       * qv;
        a1 += Wk[(size_t)a*DUx + threadIdx.x + 256] * qv;
    }
    g_qk[b*DUx + threadIdx.x]       = a0;
    g_qk[b*DUx + threadIdx.x + 256] = a1;
}

// ---------------- logits[b,t] = (u·qk/16 + sbias - sp) / temp ----------------
__global__ void k_scores(const float* __restrict__ u, const float* __restrict__ lt){
    int b  = blockIdx.x >> 8;
    int t0 = (blockIdx.x & 255) * 8;
    __shared__ float4 s_qk[DUx/4];
    for (int i = threadIdx.x; i < DUx/4; i += blockDim.x)
        s_qk[i] = ((const float4*)(g_qk + b*DUx))[i];
    __syncthreads();
    int w = threadIdx.x >> 5, lane = threadIdx.x & 31;
    int t = t0 + w, bt = b*TT + t;
    const float4* up = (const float4*)(u + (size_t)bt * DUx);
    float acc = 0.f;
    #pragma unroll
    for (int c = 0; c < 4; c++){
        float4 a = up[c*32 + lane], q = s_qk[c*32 + lane];
        acc += a.x*q.x + a.y*q.y + a.z*q.z + a.w*q.w;
    }
    acc = warpSum(acc);
    if (lane == 0){
        float temp = fminf(fmaxf(expf(lt[0]), 0.1f), 10.f);
        g_logits[bt] = (acc * INV_SCALE + g_sbias[bt] - g_sp[bt]) / temp;
    }
}

// ---------------- first softmax over T per b ----------------
__global__ void k_softmax1(){
    int b = blockIdx.x;
    int i0 = b*TT + threadIdx.x, i1 = i0 + 1024;
    __shared__ float sh[32];
    float l0 = g_logits[i0], l1 = g_logits[i1];
    float m = blockMax(fmaxf(l0, l1), sh);
    float e0 = expf(l0 - m), e1 = expf(l1 - m);
    float S = blockSum(e0 + e1, sh);
    float inv = 1.f / S;
    g_y[i0] = e0*inv; g_y[i1] = e1*inv;
}

// ---------------- sim matvec: overlap = sim@y  or  sp += sim@y ----------------
__global__ void k_simmv(const float* __restrict__ sim, int accumulate){
    int b  = blockIdx.x >> 8;
    int t0 = (blockIdx.x & 255) * 8;
    __shared__ float4 s_y[TT/4];
    for (int i = threadIdx.x; i < TT/4; i += blockDim.x)
        s_y[i] = ((const float4*)(g_y + b*TT))[i];
    __syncthreads();
    int w = threadIdx.x >> 5, lane = threadIdx.x & 31;
    int t = t0 + w, bt = b*TT + t;
    const float4* row = (const float4*)(sim + ((size_t)b*TT + t) * TT);
    float acc = 0.f;
    #pragma unroll
    for (int c = 0; c < 16; c++){
        int idx = c*32 + lane;
        float4 s4 = row[idx], y4 = s_y[idx];
        acc += s4.x*y4.x + s4.y*y4.y + s4.z*y4.z + s4.w*y4.w;
    }
    acc = warpSum(acc);
    if (lane == 0){
        if (accumulate) g_sp[bt] += acc;
        else            g_overlap[bt] = acc;
    }
}

// ---------------- penalty + second softmax + scalar stats ----------------
__global__ void k_penalty(){
    int b = blockIdx.x;
    int i0 = b*TT + threadIdx.x, i1 = i0 + 1024;
    __shared__ float sh[32];
    float o0 = g_overlap[i0], o1 = g_overlap[i1];
    float mo = blockMax(fmaxf(o0, o1), sh);
    mo = fmaxf(mo, EPSV);
    float invmo = 1.f / mo;
    float l0 = g_logits[i0] - o0*invmo;
    float l1 = g_logits[i1] - o1*invmo;
    float m = blockMax(fmaxf(l0, l1), sh);
    float e0 = expf(l0 - m), e1 = expf(l1 - m);
    float S = blockSum(e0 + e1, sh);
    float invS = 1.f / S;
    float y0 = e0*invS, y1 = e1*invS;
    g_y[i0] = y0; g_y[i1] = y1;
    float ysum = blockSum(y0 + y1, sh);
    float ys = fmaxf(ysum, EPSV);
    float invys = 1.f / ys;
    float yn0 = y0*invys, yn1 = y1*invys;
    float ent = blockSum(-yn0*logf(fmaxf(yn0, EPSV)) - yn1*logf(fmaxf(yn1, EPSV)), sh);
    float wsq = blockSum(y0*g_usq[i0] + y1*g_usq[i1], sh);
    if (threadIdx.x == 0){
        g_stat[b*8+0] = ys;
        g_stat[b*8+1] = ysum * (1.f/(float)TT);   // coverage
        g_stat[b*8+2] = ent;
        g_stat[b*8+3] = wsq;
        g_stat[b*8+4] = 0.f;                       // spread accumulator
    }
    if (threadIdx.x < DUx) g_yu[b*DUx + threadIdx.x] = 0.f;
}

// ---------------- yu = y @ u  (partial sums + atomics) ----------------
__global__ void k_yu(const float* __restrict__ u){
    int b  = blockIdx.x >> 6;
    int t0 = (blockIdx.x & 63) * 32;
    __shared__ float s_y[32];
    if (threadIdx.x < 32) s_y[threadIdx.x] = g_y[b*TT + t0 + threadIdx.x];
    __syncthreads();
    float a0 = 0.f, a1 = 0.f;
    const float* up = u + ((size_t)b*TT + t0) * DUx;
    #pragma unroll 8
    for (int i = 0; i < 32; i++){
        float yv = s_y[i];
        a0 += yv * up[(size_t)i*DUx + threadIdx.x];
        a1 += yv * up[(size_t)i*DUx + threadIdx.x + 256];
    }
    atomicAdd(&g_yu[b*DUx + threadIdx.x],       a0);
    atomicAdd(&g_yu[b*DUx + threadIdx.x + 256], a1);
}

// ---------------- spread: sum_t y_t * ||u_t - cen|| ----------------
__global__ void k_dist(const float* __restrict__ u){
    int b  = blockIdx.x >> 8;
    int t0 = (blockIdx.x & 255) * 8;
    __shared__ float4 s_cen4[DUx/4];
    __shared__ float sh[32];
    float* s_cen = (float*)s_cen4;
    float invys = 1.f / g_stat[b*8+0];
    for (int i = threadIdx.x; i < DUx; i += 256) s_cen[i] = g_yu[b*DUx + i] * invys;
    __syncthreads();
    int w = threadIdx.x >> 5, lane = threadIdx.x & 31;
    int t = t0 + w, bt = b*TT + t;
    const float4* up = (const float4*)(u + (size_t)bt * DUx);
    float acc = 0.f;
    #pragma unroll
    for (int c = 0; c < 4; c++){
        int idx = c*32 + lane;
        float4 a = up[idx], cn = s_cen4[idx];
        float dx = a.x - cn.x, dy = a.y - cn.y, dz = a.z - cn.z, dw = a.w - cn.w;
        acc += dx*dx + dy*dy + dz*dz + dw*dw;
    }
    acc = warpSum(acc);
    float part = (lane == 0) ? g_y[bt] * sqrtf(acc) : 0.f;
    float tot = blockSum(part, sh);
    if (threadIdx.x == 0) atomicAdd(&g_stat[b*8+4], tot);
}

// ---------------- z = Wv @ yu ; write out + build x = [z, c] ----------------
__global__ void k_zx(const float* __restrict__ Wv, float* __restrict__ out, int stage){
    int b = blockIdx.x >> 3;
    int c = blockIdx.x & 7;
    __shared__ float4 s_yu4[DUx/4];
    __shared__ float sh[32];
    float* s_yu = (float*)s_yu4;
    for (int i = threadIdx.x; i < DUx; i += 256) s_yu[i] = g_yu[b*DUx + i];
    __syncthreads();
    int w = threadIdx.x >> 5, lane = threadIdx.x & 31;
    #pragma unroll
    for (int j = 0; j < 8; j++){
        int d = c*64 + w*8 + j;
        const float4* row = (const float4*)(Wv + (size_t)d * DUx);
        float acc = 0.f;
        #pragma unroll
        for (int cc = 0; cc < 4; cc++){
            int idx = cc*32 + lane;
            float4 a = row[idx], yv = s_yu4[idx];
            acc += a.x*yv.x + a.y*yv.y + a.z*yv.z + a.w*yv.w;
        }
        acc = warpSum(acc);
        if (lane == 0){
            out[((size_t)b*NSTAGE + stage)*DUx + d] = acc;
            g_x[b*DXx + d] = acc;
        }
    }
    if (c == 0){
        float v0 = s_yu[threadIdx.x], v1 = s_yu[threadIdx.x + 256];
        float csq = blockSum(v0*v0 + v1*v1, sh);
        if (threadIdx.x == 0){
            float ys  = g_stat[b*8+0];
            float compact = 2.f * (ys * g_stat[b*8+3] - csq) / fmaxf(ys*ys, EPSV);
            g_x[b*DXx + 512] = g_stat[b*8+1];          // coverage
            g_x[b*DXx + 513] = g_stat[b*8+2];          // entropy
            g_x[b*DXx + 514] = g_stat[b*8+4] / ys;     // spread
            g_x[b*DXx + 515] = compact;
        }
    }
}

// ---------------- GRU cell update (double-buffered memory) ----------------
__global__ void k_gru(const float* __restrict__ W_ih, const float* __restrict__ b_ih,
                      const float* __restrict__ W_hh, const float* __restrict__ b_hh,
                      int inB){
    const float* mem_in  = inB ? g_memB : g_memA;
    float*       mem_out = inB ? g_memA : g_memB;
    int b = blockIdx.x >> 3;
    int c = blockIdx.x & 7;
    __shared__ float4 s_x4[DXx/4];   // 129 float4
    __shared__ float4 s_m4[DMx/4];
    float* s_x = (float*)s_x4; float* s_m = (float*)s_m4;
    for (int i = threadIdx.x; i < DXx; i += 256) s_x[i] = g_x[b*DXx + i];
    for (int i = threadIdx.x; i < DMx; i += 256) s_m[i] = mem_in[b*DMx + i];
    __syncthreads();
    int w = threadIdx.x >> 5, lane = threadIdx.x & 31;
    for (int jj = 0; jj < 8; jj++){
        int j = c*64 + w*8 + jj;
        float gi[3], gh[3];
        #pragma unroll
        for (int g = 0; g < 3; g++){
            int r = j + g*DMx;
            const float4* wi = (const float4*)(W_ih + (size_t)r * DXx);
            float acc = 0.f;
            #pragma unroll
            for (int cc = 0; cc < 4; cc++){
                int idx = cc*32 + lane;
                float4 a = wi[idx], xx = s_x4[idx];
                acc += a.x*xx.x + a.y*xx.y + a.z*xx.z + a.w*xx.w;
            }
            if (lane == 0){
                float4 a = wi[128], xx = s_x4[128];  // tail elems 512..515
                acc += a.x*xx.x + a.y*xx.y + a.z*xx.z + a.w*xx.w;
            }
            acc = warpSum(acc);
            gi[g] = acc + b_ih[r];

            const float4* wh = (const float4*)(W_hh + (size_t)r * DMx);
            float acch = 0.f;
            #pragma unroll
            for (int cc = 0; cc < 4; cc++){
                int idx = cc*32 + lane;
                float4 a = wh[idx], mm = s_m4[idx];
                acch += a.x*mm.x + a.y*mm.y + a.z*mm.z + a.w*mm.w;
            }
            acch = warpSum(acch);
            gh[g] = acch + b_hh[r];
        }
        if (lane == 0){
            float rg = 1.f / (1.f + expf(-(gi[0] + gh[0])));
            float zg = 1.f / (1.f + expf(-(gi[1] + gh[1])));
            float ng = tanhf(gi[2] + rg * gh[2]);
            mem_out[b*DMx + j] = (1.f - zg) * ng + zg * s_m[j];
        }
    }
}

// ---------------- launch ----------------
extern "C" void kernel_launch(void* const* d_in, const int* in_sizes, int n_in,
                              void* d_out, int out_size){
    const float* u    = (const float*)d_in[0];
    const float* sf   = (const float*)d_in[1];
    const float* sim  = (const float*)d_in[2];
    const float* mem0 = (const float*)d_in[3];
    const float* Wq   = (const float*)d_in[4];
    const float* Wk   = (const float*)d_in[5];
    const float* Wv   = (const float*)d_in[6];
    const float* sbw1 = (const float*)d_in[7];
    const float* sbb1 = (const float*)d_in[8];
    const float* sbw2 = (const float*)d_in[9];
    const float* sbb2 = (const float*)d_in[10];
    const float* lt   = (const float*)d_in[11];
    const float* Wih  = (const float*)d_in[12];
    const float* bih  = (const float*)d_in[13];
    const float* Whh  = (const float*)d_in[14];
    const float* bhh  = (const float*)d_in[15];
    float* out = (float*)d_out;

    k_init<<<64, 256>>>(mem0);
    k_pre<<<BB*TT/8, 256>>>(u, sf, sbw1, sbb1, sbw2, sbb2);

    for (int s = 0; s < NSTAGE; s++){
        int inB = s & 1;
        k_qqk<<<BB, 256>>>(Wq, Wk, inB);
        k_scores<<<BB*TT/8, 256>>>(u, lt);
        k_softmax1<<<BB, 1024>>>();
        k_simmv<<<BB*TT/8, 256>>>(sim, 0);        // overlap = sim @ y_pre
        k_penalty<<<BB, 1024>>>();                // y_final + scalar stats
        k_yu<<<BB*64, 256>>>(u);                  // centroid (raw)
        k_dist<<<BB*TT/8, 256>>>(u);              // spread
        k_zx<<<BB*8, 256>>>(Wv, out, s);          // z = Wv@yu, x = [z,c]
        k_gru<<<BB*8, 256>>>(Wih, bih, Whh, bhh, inB);
        if (s < NSTAGE - 1)
            k_simmv<<<BB*TT/8, 256>>>(sim, 1);    // sp += sim @ y_final
    }
}

// round 5
// speedup vs baseline: 1.1520x; 1.1520x over previous
#include <cuda_runtime.h>
#include <cuda_fp16.h>
#include <math.h>

#define BB 8
#define TT 2048
#define DUx 512
#define DMx 512
#define DAx 256
#define DFx 12
#define DXx 516
#define NSTAGE 4
#define EPSV 1e-6f
#define INV_SCALE (1.0f/16.0f)

// ---------------- scratch (device globals; no allocation) ----------------
__device__ float g_usq[BB*TT];
__device__ float g_sbias[BB*TT];
__device__ float g_logits[BB*TT];
__device__ float g_y[BB*TT];
__device__ float g_overlap[BB*TT];
__device__ float g_sp[BB*TT];      // sim @ prev (accumulated)
__device__ float g_yu[BB*DUx];     // y @ u  (raw centroid)
__device__ float g_x[BB*DXx];      // GRU input [z, c]
__device__ float g_memA[BB*DMx];
__device__ float g_memB[BB*DMx];
__device__ float g_qk[BB*DUx];     // Wk^T @ q
__device__ float g_stat[BB*8];     // [ysum_clamped, coverage, entropy, wsq, spread_acc]

// fp16 compressed copies (written once, read many)
__device__ __half g_simh[(size_t)BB*TT*TT];   // 67 MB
__device__ __half g_uh[(size_t)BB*TT*DUx];    // 17 MB

// ---------------- reduction helpers ----------------
__device__ __forceinline__ float warpSum(float v){
    #pragma unroll
    for (int o = 16; o; o >>= 1) v += __shfl_xor_sync(0xffffffffu, v, o);
    return v;
}
__device__ __forceinline__ float warpMax(float v){
    #pragma unroll
    for (int o = 16; o; o >>= 1) v = fmaxf(v, __shfl_xor_sync(0xffffffffu, v, o));
    return v;
}
__device__ __forceinline__ float blockSum(float v, float* sh){
    int lane = threadIdx.x & 31, w = threadIdx.x >> 5;
    int nw = (blockDim.x + 31) >> 5;
    v = warpSum(v);
    if (lane == 0) sh[w] = v;
    __syncthreads();
    if (w == 0){
        float x = (lane < nw) ? sh[lane] : 0.f;
        x = warpSum(x);
        if (lane == 0) sh[0] = x;
    }
    __syncthreads();
    float r = sh[0];
    __syncthreads();
    return r;
}
__device__ __forceinline__ float blockMax(float v, float* sh){
    int lane = threadIdx.x & 31, w = threadIdx.x >> 5;
    int nw = (blockDim.x + 31) >> 5;
    v = warpMax(v);
    if (lane == 0) sh[w] = v;
    __syncthreads();
    if (w == 0){
        float x = (lane < nw) ? sh[lane] : -INFINITY;
        x = warpMax(x);
        if (lane == 0) sh[0] = x;
    }
    __syncthreads();
    float r = sh[0];
    __syncthreads();
    return r;
}

// ---------------- init: zero sp, copy memory0 ----------------
__global__ void k_init(const float* __restrict__ mem0){
    int i = blockIdx.x * blockDim.x + threadIdx.x;
    if (i < BB*TT) g_sp[i] = 0.f;
    if (i < BB*DMx) g_memA[i] = mem0[i];
}

// ---------------- precompute: usq[b,t], sbias[b,t], u -> fp16 ----------------
__global__ void k_pre(const float* __restrict__ u, const float* __restrict__ sf,
                      const float* __restrict__ w1, const float* __restrict__ b1,
                      const float* __restrict__ w2, const float* __restrict__ b2){
    int b  = blockIdx.x >> 8;
    int t0 = (blockIdx.x & 255) * 8;
    int w = threadIdx.x >> 5, lane = threadIdx.x & 31;
    int t = t0 + w, bt = b*TT + t;
    const float4* up = (const float4*)(u + (size_t)bt * DUx);   // 128 float4
    int4* uo = (int4*)(g_uh + (size_t)bt * DUx);                // 64 int4 (8 halves each)
    float acc = 0.f;
    #pragma unroll
    for (int c = 0; c < 2; c++){
        int idx = c*32 + lane;
        float4 f0 = up[2*idx], f1 = up[2*idx+1];
        acc += f0.x*f0.x + f0.y*f0.y + f0.z*f0.z + f0.w*f0.w
             + f1.x*f1.x + f1.y*f1.y + f1.z*f1.z + f1.w*f1.w;
        __half2 h0 = __floats2half2_rn(f0.x, f0.y);
        __half2 h1 = __floats2half2_rn(f0.z, f0.w);
        __half2 h2 = __floats2half2_rn(f1.x, f1.y);
        __half2 h3 = __floats2half2_rn(f1.z, f1.w);
        int4 o;
        o.x = *(int*)&h0; o.y = *(int*)&h1; o.z = *(int*)&h2; o.w = *(int*)&h3;
        uo[idx] = o;
    }
    acc = warpSum(acc);
    float d0 = sf[bt*DFx + 8], d1 = sf[bt*DFx + 9], d2 = sf[bt*DFx + 10];
    float sb = 0.f;
    #pragma unroll
    for (int k = 0; k < 8; k++){
        int a = lane + k*32;
        float h = w1[a*3+0]*d0 + w1[a*3+1]*d1 + w1[a*3+2]*d2 + b1[a];
        h = 0.5f * h * (1.f + erff(h * 0.70710678118654752f));  // exact GELU
        sb += h * w2[a];
    }
    sb = warpSum(sb);
    if (lane == 0){ g_usq[bt] = acc; g_sbias[bt] = sb + b2[0]; }
}

// ---------------- q = Wq@mem ; qk = Wk^T@q ----------------
__global__ void k_qqk(const float* __restrict__ Wq, const float* __restrict__ Wk, int inB){
    const float* mem_in = inB ? g_memB : g_memA;
    int b = blockIdx.x;
    __shared__ float4 s_m4[DMx/4];
    __shared__ float s_q[DAx];
    float* s_m = (float*)s_m4;
    for (int i = threadIdx.x; i < DMx; i += 256) s_m[i] = mem_in[b*DMx + i];
    __syncthreads();
    int w = threadIdx.x >> 5, lane = threadIdx.x & 31;
    for (int k = 0; k < 32; k++){
        int a = w*32 + k;
        const float4* row = (const float4*)(Wq + (size_t)a * DMx);
        float acc = 0.f;
        #pragma unroll
        for (int cc = 0; cc < 4; cc++){
            float4 r4 = row[cc*32 + lane], m4 = s_m4[cc*32 + lane];
            acc += r4.x*m4.x + r4.y*m4.y + r4.z*m4.z + r4.w*m4.w;
        }
        acc = warpSum(acc);
        if (lane == 0) s_q[a] = acc;
    }
    __syncthreads();
    float a0 = 0.f, a1 = 0.f;
    for (int a = 0; a < DAx; a++){
        float qv = s_q[a];
        a0 += Wk[(size_t)a*DUx + threadIdx.x]       * qv;
        a1 += Wk[(size_t)a*DUx + threadIdx.x + 256] * qv;
    }
    g_qk[b*DUx + threadIdx.x]       = a0;
    g_qk[b*DUx + threadIdx.x + 256] = a1;
}

// ---------------- logits[b,t] = (u·qk/16 + sbias - sp) / temp  (fp16 u) ----------------
__global__ void k_scores(const float* __restrict__ lt){
    int b  = blockIdx.x >> 8;
    int t0 = (blockIdx.x & 255) * 8;
    __shared__ float2 s_qk2[DUx/2];
    for (int i = threadIdx.x; i < DUx/2; i += blockDim.x)
        s_qk2[i] = ((const float2*)(g_qk + b*DUx))[i];
    __syncthreads();
    int w = threadIdx.x >> 5, lane = threadIdx.x & 31;
    int t = t0 + w, bt = b*TT + t;
    const int4* rowh = (const int4*)(g_uh + (size_t)bt * DUx);  // 64 int4
    float acc = 0.f;
    #pragma unroll
    for (int c = 0; c < 2; c++){
        int idx = c*32 + lane;
        int4 h = rowh[idx];
        __half2* hp = (__half2*)&h;
        #pragma unroll
        for (int j = 0; j < 4; j++){
            float2 uv = __half22float2(hp[j]);
            float2 qv = s_qk2[idx*4 + j];
            acc += uv.x*qv.x + uv.y*qv.y;
        }
    }
    acc = warpSum(acc);
    if (lane == 0){
        float temp = fminf(fmaxf(expf(lt[0]), 0.1f), 10.f);
        g_logits[bt] = (acc * INV_SCALE + g_sbias[bt] - g_sp[bt]) / temp;
    }
}

// ---------------- first softmax over T per b ----------------
__global__ void k_softmax1(){
    int b = blockIdx.x;
    int i0 = b*TT + threadIdx.x, i1 = i0 + 1024;
    __shared__ float sh[32];
    float l0 = g_logits[i0], l1 = g_logits[i1];
    float m = blockMax(fmaxf(l0, l1), sh);
    float e0 = expf(l0 - m), e1 = expf(l1 - m);
    float S = blockSum(e0 + e1, sh);
    float inv = 1.f / S;
    g_y[i0] = e0*inv; g_y[i1] = e1*inv;
}

// ---------------- stage-0 overlap: read fp32 sim, compute sim@y, emit fp16 sim ----------------
__global__ void k_simmv_conv(const float* __restrict__ sim){
    int b  = blockIdx.x >> 8;
    int t0 = (blockIdx.x & 255) * 8;
    __shared__ float4 s_y4[TT/4];
    for (int i = threadIdx.x; i < TT/4; i += blockDim.x)
        s_y4[i] = ((const float4*)(g_y + b*TT))[i];
    __syncthreads();
    int w = threadIdx.x >> 5, lane = threadIdx.x & 31;
    int t = t0 + w, bt = b*TT + t;
    const float4* row = (const float4*)(sim + (size_t)bt * TT);
    int4* out = (int4*)(g_simh + (size_t)bt * TT);
    float acc = 0.f;
    #pragma unroll
    for (int c = 0; c < 8; c++){
        int idx = c*32 + lane;
        float4 f0 = row[2*idx], f1 = row[2*idx+1];
        float4 y0 = s_y4[2*idx], y1 = s_y4[2*idx+1];
        acc += f0.x*y0.x + f0.y*y0.y + f0.z*y0.z + f0.w*y0.w
             + f1.x*y1.x + f1.y*y1.y + f1.z*y1.z + f1.w*y1.w;
        __half2 h0 = __floats2half2_rn(f0.x, f0.y);
        __half2 h1 = __floats2half2_rn(f0.z, f0.w);
        __half2 h2 = __floats2half2_rn(f1.x, f1.y);
        __half2 h3 = __floats2half2_rn(f1.z, f1.w);
        int4 o;
        o.x = *(int*)&h0; o.y = *(int*)&h1; o.z = *(int*)&h2; o.w = *(int*)&h3;
        out[idx] = o;
    }
    acc = warpSum(acc);
    if (lane == 0) g_overlap[bt] = acc;
}

// ---------------- fp16 sim matvec: overlap = sim@y  or  sp += sim@y ----------------
__global__ void k_simmv_h(int accumulate){
    int b  = blockIdx.x >> 8;
    int t0 = (blockIdx.x & 255) * 8;
    __shared__ float2 s_y2[TT/2];
    for (int i = threadIdx.x; i < TT/2; i += blockDim.x)
        s_y2[i] = ((const float2*)(g_y + b*TT))[i];
    __syncthreads();
    int w = threadIdx.x >> 5, lane = threadIdx.x & 31;
    int t = t0 + w, bt = b*TT + t;
    const int4* row = (const int4*)(g_simh + (size_t)bt * TT);  // 256 int4
    float acc = 0.f;
    #pragma unroll
    for (int c = 0; c < 8; c++){
        int idx = c*32 + lane;
        int4 h = row[idx];
        __half2* hp = (__half2*)&h;
        #pragma unroll
        for (int j = 0; j < 4; j++){
            float2 sv = __half22float2(hp[j]);
            float2 yv = s_y2[idx*4 + j];
            acc += sv.x*yv.x + sv.y*yv.y;
        }
    }
    acc = warpSum(acc);
    if (lane == 0){
        if (accumulate) g_sp[bt] += acc;
        else            g_overlap[bt] = acc;
    }
}

// ---------------- penalty + second softmax + scalar stats ----------------
__global__ void k_penalty(){
    int b = blockIdx.x;
    int i0 = b*TT + threadIdx.x, i1 = i0 + 1024;
    __shared__ float sh[32];
    float o0 = g_overlap[i0], o1 = g_overlap[i1];
    float mo = blockMax(fmaxf(o0, o1), sh);
    mo = fmaxf(mo, EPSV);
    float invmo = 1.f / mo;
    float l0 = g_logits[i0] - o0*invmo;
    float l1 = g_logits[i1] - o1*invmo;
    float m = blockMax(fmaxf(l0, l1), sh);
    float e0 = expf(l0 - m), e1 = expf(l1 - m);
    float S = blockSum(e0 + e1, sh);
    float invS = 1.f / S;
    float y0 = e0*invS, y1 = e1*invS;
    g_y[i0] = y0; g_y[i1] = y1;
    float ysum = blockSum(y0 + y1, sh);
    float ys = fmaxf(ysum, EPSV);
    float invys = 1.f / ys;
    float yn0 = y0*invys, yn1 = y1*invys;
    float ent = blockSum(-yn0*logf(fmaxf(yn0, EPSV)) - yn1*logf(fmaxf(yn1, EPSV)), sh);
    float wsq = blockSum(y0*g_usq[i0] + y1*g_usq[i1], sh);
    if (threadIdx.x == 0){
        g_stat[b*8+0] = ys;
        g_stat[b*8+1] = ysum * (1.f/(float)TT);   // coverage
        g_stat[b*8+2] = ent;
        g_stat[b*8+3] = wsq;
        g_stat[b*8+4] = 0.f;                       // spread accumulator
    }
    if (threadIdx.x < DUx) g_yu[b*DUx + threadIdx.x] = 0.f;
}

// ---------------- yu = y @ u (fp16 u; partial sums + atomics) ----------------
__global__ void k_yu(){
    int b  = blockIdx.x >> 6;
    int t0 = (blockIdx.x & 63) * 32;
    __shared__ float s_y[32];
    if (threadIdx.x < 32) s_y[threadIdx.x] = g_y[b*TT + t0 + threadIdx.x];
    __syncthreads();
    float ax = 0.f, ay = 0.f;
    const __half2* up = (const __half2*)(g_uh + ((size_t)b*TT + t0) * DUx);
    // row stride = DUx/2 = 256 half2; thread handles cols (2*tid, 2*tid+1)
    #pragma unroll 8
    for (int i = 0; i < 32; i++){
        float yv = s_y[i];
        float2 v = __half22float2(up[i*256 + threadIdx.x]);
        ax += yv * v.x; ay += yv * v.y;
    }
    atomicAdd(&g_yu[b*DUx + 2*threadIdx.x],     ax);
    atomicAdd(&g_yu[b*DUx + 2*threadIdx.x + 1], ay);
}

// ---------------- spread: sum_t y_t * ||u_t - cen||  (fp16 u) ----------------
__global__ void k_dist(){
    int b  = blockIdx.x >> 8;
    int t0 = (blockIdx.x & 255) * 8;
    __shared__ float2 s_cen2[DUx/2];
    __shared__ float sh[32];
    float invys = 1.f / g_stat[b*8+0];
    for (int i = threadIdx.x; i < DUx/2; i += 256){
        float2 c2 = ((const float2*)(g_yu + b*DUx))[i];
        s_cen2[i] = make_float2(c2.x*invys, c2.y*invys);
    }
    __syncthreads();
    int w = threadIdx.x >> 5, lane = threadIdx.x & 31;
    int t = t0 + w, bt = b*TT + t;
    const int4* rowh = (const int4*)(g_uh + (size_t)bt * DUx);
    float acc = 0.f;
    #pragma unroll
    for (int c = 0; c < 2; c++){
        int idx = c*32 + lane;
        int4 h = rowh[idx];
        __half2* hp = (__half2*)&h;
        #pragma unroll
        for (int j = 0; j < 4; j++){
            float2 uv = __half22float2(hp[j]);
            float2 cn = s_cen2[idx*4 + j];
            float dx = uv.x - cn.x, dy = uv.y - cn.y;
            acc += dx*dx + dy*dy;
        }
    }
    acc = warpSum(acc);
    float part = (lane == 0) ? g_y[bt] * sqrtf(acc) : 0.f;
    float tot = blockSum(part, sh);
    if (threadIdx.x == 0) atomicAdd(&g_stat[b*8+4], tot);
}

// ---------------- z = Wv @ yu ; write out + build x = [z, c] ----------------
__global__ void k_zx(const float* __restrict__ Wv, float* __restrict__ out, int stage){
    int b = blockIdx.x >> 3;
    int c = blockIdx.x & 7;
    __shared__ float4 s_yu4[DUx/4];
    __shared__ float sh[32];
    float* s_yu = (float*)s_yu4;
    for (int i = threadIdx.x; i < DUx; i += 256) s_yu[i] = g_yu[b*DUx + i];
    __syncthreads();
    int w = threadIdx.x >> 5, lane = threadIdx.x & 31;
    #pragma unroll
    for (int j = 0; j < 8; j++){
        int d = c*64 + w*8 + j;
        const float4* row = (const float4*)(Wv + (size_t)d * DUx);
        float acc = 0.f;
        #pragma unroll
        for (int cc = 0; cc < 4; cc++){
            int idx = cc*32 + lane;
            float4 a = row[idx], yv = s_yu4[idx];
            acc += a.x*yv.x + a.y*yv.y + a.z*yv.z + a.w*yv.w;
        }
        acc = warpSum(acc);
        if (lane == 0){
            out[((size_t)b*NSTAGE + stage)*DUx + d] = acc;
            g_x[b*DXx + d] = acc;
        }
    }
    if (c == 0){
        float v0 = s_yu[threadIdx.x], v1 = s_yu[threadIdx.x + 256];
        float csq = blockSum(v0*v0 + v1*v1, sh);
        if (threadIdx.x == 0){
            float ys  = g_stat[b*8+0];
            float compact = 2.f * (ys * g_stat[b*8+3] - csq) / fmaxf(ys*ys, EPSV);
            g_x[b*DXx + 512] = g_stat[b*8+1];          // coverage
            g_x[b*DXx + 513] = g_stat[b*8+2];          // entropy
            g_x[b*DXx + 514] = g_stat[b*8+4] / ys;     // spread
            g_x[b*DXx + 515] = compact;
        }
    }
}

// ---------------- GRU cell update (double-buffered memory) ----------------
__global__ void k_gru(const float* __restrict__ W_ih, const float* __restrict__ b_ih,
                      const float* __restrict__ W_hh, const float* __restrict__ b_hh,
                      int inB){
    const float* mem_in  = inB ? g_memB : g_memA;
    float*       mem_out = inB ? g_memA : g_memB;
    int b = blockIdx.x >> 3;
    int c = blockIdx.x & 7;
    __shared__ float4 s_x4[DXx/4];   // 129 float4
    __shared__ float4 s_m4[DMx/4];
    float* s_x = (float*)s_x4; float* s_m = (float*)s_m4;
    for (int i = threadIdx.x; i < DXx; i += 256) s_x[i] = g_x[b*DXx + i];
    for (int i = threadIdx.x; i < DMx; i += 256) s_m[i] = mem_in[b*DMx + i];
    __syncthreads();
    int w = threadIdx.x >> 5, lane = threadIdx.x & 31;
    for (int jj = 0; jj < 8; jj++){
        int j = c*64 + w*8 + jj;
        float gi[3], gh[3];
        #pragma unroll
        for (int g = 0; g < 3; g++){
            int r = j + g*DMx;
            const float4* wi = (const float4*)(W_ih + (size_t)r * DXx);
            float acc = 0.f;
            #pragma unroll
            for (int cc = 0; cc < 4; cc++){
                int idx = cc*32 + lane;
                float4 a = wi[idx], xx = s_x4[idx];
                acc += a.x*xx.x + a.y*xx.y + a.z*xx.z + a.w*xx.w;
            }
            if (lane == 0){
                float4 a = wi[128], xx = s_x4[128];  // tail elems 512..515
                acc += a.x*xx.x + a.y*xx.y + a.z*xx.z + a.w*xx.w;
            }
            acc = warpSum(acc);
            gi[g] = acc + b_ih[r];

            const float4* wh = (const float4*)(W_hh + (size_t)r * DMx);
            float acch = 0.f;
            #pragma unroll
            for (int cc = 0; cc < 4; cc++){
                int idx = cc*32 + lane;
                float4 a = wh[idx], mm = s_m4[idx];
                acch += a.x*mm.x + a.y*mm.y + a.z*mm.z + a.w*mm.w;
            }
            acch = warpSum(acch);
            gh[g] = acch + b_hh[r];
        }
        if (lane == 0){
            float rg = 1.f / (1.f + expf(-(gi[0] + gh[0])));
            float zg = 1.f / (1.f + expf(-(gi[1] + gh[1])));
            float ng = tanhf(gi[2] + rg * gh[2]);
            mem_out[b*DMx + j] = (1.f - zg) * ng + zg * s_m[j];
        }
    }
}

// ---------------- launch ----------------
extern "C" void kernel_launch(void* const* d_in, const int* in_sizes, int n_in,
                              void* d_out, int out_size){
    const float* u    = (const float*)d_in[0];
    const float* sf   = (const float*)d_in[1];
    const float* sim  = (const float*)d_in[2];
    const float* mem0 = (const float*)d_in[3];
    const float* Wq   = (const float*)d_in[4];
    const float* Wk   = (const float*)d_in[5];
    const float* Wv   = (const float*)d_in[6];
    const float* sbw1 = (const float*)d_in[7];
    const float* sbb1 = (const float*)d_in[8];
    const float* sbw2 = (const float*)d_in[9];
    const float* sbb2 = (const float*)d_in[10];
    const float* lt   = (const float*)d_in[11];
    const float* Wih  = (const float*)d_in[12];
    const float* bih  = (const float*)d_in[13];
    const float* Whh  = (const float*)d_in[14];
    const float* bhh  = (const float*)d_in[15];
    float* out = (float*)d_out;

    k_init<<<64, 256>>>(mem0);
    k_pre<<<BB*TT/8, 256>>>(u, sf, sbw1, sbb1, sbw2, sbb2);

    for (int s = 0; s < NSTAGE; s++){
        int inB = s & 1;
        k_qqk<<<BB, 256>>>(Wq, Wk, inB);
        k_scores<<<BB*TT/8, 256>>>(lt);
        k_softmax1<<<BB, 1024>>>();
        if (s == 0)
            k_simmv_conv<<<BB*TT/8, 256>>>(sim);   // overlap + fp16 compress
        else
            k_simmv_h<<<BB*TT/8, 256>>>(0);        // overlap = sim @ y_pre
        k_penalty<<<BB, 1024>>>();                 // y_final + scalar stats
        k_yu<<<BB*64, 256>>>();                    // centroid (raw)
        k_dist<<<BB*TT/8, 256>>>();                // spread
        k_zx<<<BB*8, 256>>>(Wv, out, s);           // z = Wv@yu, x = [z,c]
        k_gru<<<BB*8, 256>>>(Wih, bih, Whh, bhh, inB);
        if (s < NSTAGE - 1)
            k_simmv_h<<<BB*TT/8, 256>>>(1);        // sp += sim @ y_final
    }
}

// round 6
// speedup vs baseline: 1.6335x; 1.4180x over previous
#include <cuda_runtime.h>
#include <cuda_fp16.h>
#include <math.h>

#define BB 8
#define TT 2048
#define DUx 512
#define DMx 512
#define DAx 256
#define DFx 12
#define DXx 516
#define NSTAGE 4
#define EPSV 1e-6f
#define INV_SCALE (1.0f/16.0f)

// ---------------- scratch (device globals; no allocation) ----------------
__device__ float g_usq[BB*TT];
__device__ float g_sbias[BB*TT];
__device__ float g_base[BB*TT];    // u·qk/16 + sbias (pre sp/temp)
__device__ float g_logits[BB*TT];  // post sp/temp (softmax input, reused by penalty)
__device__ float g_y[BB*TT];
__device__ float g_overlap[BB*TT];
__device__ float g_sp[BB*TT];      // sim @ prev (accumulated)
__device__ float g_yu[BB*DUx];     // y @ u  (raw centroid)
__device__ float g_x[BB*DXx];      // GRU input [z, c]
__device__ float g_memA[BB*DMx];
__device__ float g_memB[BB*DMx];
__device__ float g_qk[BB*DUx];     // M @ mem
__device__ float g_stat[BB*8];
__device__ float g_M[DUx*DMx];     // Wk^T @ Wq  (512 x 512)

// fp16 compressed copies (written once, read many)
__device__ __half g_simh[(size_t)BB*TT*TT];   // 67 MB
__device__ __half g_uh[(size_t)BB*TT*DUx];    // 17 MB

// ---------------- reduction helpers ----------------
__device__ __forceinline__ float warpSum(float v){
    #pragma unroll
    for (int o = 16; o; o >>= 1) v += __shfl_xor_sync(0xffffffffu, v, o);
    return v;
}
__device__ __forceinline__ float warpMax(float v){
    #pragma unroll
    for (int o = 16; o; o >>= 1) v = fmaxf(v, __shfl_xor_sync(0xffffffffu, v, o));
    return v;
}
__device__ __forceinline__ float blockSum(float v, float* sh){
    int lane = threadIdx.x & 31, w = threadIdx.x >> 5;
    int nw = (blockDim.x + 31) >> 5;
    v = warpSum(v);
    if (lane == 0) sh[w] = v;
    __syncthreads();
    if (w == 0){
        float x = (lane < nw) ? sh[lane] : 0.f;
        x = warpSum(x);
        if (lane == 0) sh[0] = x;
    }
    __syncthreads();
    float r = sh[0];
    __syncthreads();
    return r;
}
__device__ __forceinline__ float blockMax(float v, float* sh){
    int lane = threadIdx.x & 31, w = threadIdx.x >> 5;
    int nw = (blockDim.x + 31) >> 5;
    v = warpMax(v);
    if (lane == 0) sh[w] = v;
    __syncthreads();
    if (w == 0){
        float x = (lane < nw) ? sh[lane] : -INFINITY;
        x = warpMax(x);
        if (lane == 0) sh[0] = x;
    }
    __syncthreads();
    float r = sh[0];
    __syncthreads();
    return r;
}

// ---------------- init: zero sp, copy memory0 ----------------
__global__ void k_init(const float* __restrict__ mem0){
    int i = blockIdx.x * blockDim.x + threadIdx.x;
    if (i < BB*TT) g_sp[i] = 0.f;
    if (i < BB*DMx) g_memA[i] = mem0[i];
}

// ---------------- M = Wk^T @ Wq  (512x512, K=256), tiled ----------------
__global__ void k_Mpre(const float* __restrict__ Wk, const float* __restrict__ Wq){
    int bm = blockIdx.x & 15, bd = blockIdx.x >> 4;
    int d0 = bd*32, m0 = bm*32;
    __shared__ float sA[32*32];   // sA[a][d]
    __shared__ float sB[32*32];   // sB[a][m]
    float acc[4] = {0.f, 0.f, 0.f, 0.f};
    int tx = threadIdx.x & 31, ty = threadIdx.x >> 5;   // ty in 0..7
    for (int a0 = 0; a0 < DAx; a0 += 32){
        __syncthreads();
        for (int i = threadIdx.x; i < 1024; i += 256){
            int ar = i >> 5, col = i & 31;
            sA[i] = Wk[(size_t)(a0+ar)*DUx + d0 + col];
            sB[i] = Wq[(size_t)(a0+ar)*DMx + m0 + col];
        }
        __syncthreads();
        #pragma unroll
        for (int aa = 0; aa < 32; aa++){
            float bv = sB[aa*32 + tx];
            #pragma unroll
            for (int r = 0; r < 4; r++)
                acc[r] += sA[aa*32 + ty + r*8] * bv;
        }
    }
    #pragma unroll
    for (int r = 0; r < 4; r++)
        g_M[(size_t)(d0 + ty + r*8)*DMx + m0 + tx] = acc[r];
}

// ---------------- precompute: usq[b,t], sbias[b,t], u -> fp16 ----------------
__global__ void k_pre(const float* __restrict__ u, const float* __restrict__ sf,
                      const float* __restrict__ w1, const float* __restrict__ b1,
                      const float* __restrict__ w2, const float* __restrict__ b2){
    int b  = blockIdx.x >> 8;
    int t0 = (blockIdx.x & 255) * 8;
    int w = threadIdx.x >> 5, lane = threadIdx.x & 31;
    int t = t0 + w, bt = b*TT + t;
    const float4* up = (const float4*)(u + (size_t)bt * DUx);
    int4* uo = (int4*)(g_uh + (size_t)bt * DUx);
    float acc = 0.f;
    #pragma unroll
    for (int c = 0; c < 2; c++){
        int idx = c*32 + lane;
        float4 f0 = up[2*idx], f1 = up[2*idx+1];
        acc += f0.x*f0.x + f0.y*f0.y + f0.z*f0.z + f0.w*f0.w
             + f1.x*f1.x + f1.y*f1.y + f1.z*f1.z + f1.w*f1.w;
        __half2 h0 = __floats2half2_rn(f0.x, f0.y);
        __half2 h1 = __floats2half2_rn(f0.z, f0.w);
        __half2 h2 = __floats2half2_rn(f1.x, f1.y);
        __half2 h3 = __floats2half2_rn(f1.z, f1.w);
        int4 o;
        o.x = *(int*)&h0; o.y = *(int*)&h1; o.z = *(int*)&h2; o.w = *(int*)&h3;
        uo[idx] = o;
    }
    acc = warpSum(acc);
    float d0 = sf[bt*DFx + 8], d1 = sf[bt*DFx + 9], d2 = sf[bt*DFx + 10];
    float sb = 0.f;
    #pragma unroll
    for (int k = 0; k < 8; k++){
        int a = lane + k*32;
        float h = w1[a*3+0]*d0 + w1[a*3+1]*d1 + w1[a*3+2]*d2 + b1[a];
        h = 0.5f * h * (1.f + erff(h * 0.70710678118654752f));
        sb += h * w2[a];
    }
    sb = warpSum(sb);
    if (lane == 0){ g_usq[bt] = acc; g_sbias[bt] = sb + b2[0]; }
}

// ---------------- qk[b,:] = M @ mem[b,:] ----------------
__global__ void k_qk(int inB){
    const float* mem_in = inB ? g_memB : g_memA;
    int b = blockIdx.x >> 4;
    int c = blockIdx.x & 15;
    __shared__ float4 s_m4[DMx/4];
    for (int i = threadIdx.x; i < DMx/4; i += 256)
        s_m4[i] = ((const float4*)(mem_in + b*DMx))[i];
    __syncthreads();
    int w = threadIdx.x >> 5, lane = threadIdx.x & 31;
    #pragma unroll
    for (int j = 0; j < 4; j++){
        int d = c*32 + w*4 + j;
        const float4* row = (const float4*)(g_M + (size_t)d * DMx);
        float acc = 0.f;
        #pragma unroll
        for (int cc = 0; cc < 4; cc++){
            int idx = cc*32 + lane;
            float4 a = row[idx], m4 = s_m4[idx];
            acc += a.x*m4.x + a.y*m4.y + a.z*m4.z + a.w*m4.w;
        }
        acc = warpSum(acc);
        if (lane == 0) g_qk[b*DUx + d] = acc;
    }
}

// ---------------- base[b,t] = u·qk/16 + sbias  (no sp/temp here) ----------------
__global__ void k_scores(){
    int b  = blockIdx.x >> 8;
    int t0 = (blockIdx.x & 255) * 8;
    __shared__ float2 s_qk2[DUx/2];
    for (int i = threadIdx.x; i < DUx/2; i += blockDim.x)
        s_qk2[i] = ((const float2*)(g_qk + b*DUx))[i];
    __syncthreads();
    int w = threadIdx.x >> 5, lane = threadIdx.x & 31;
    int t = t0 + w, bt = b*TT + t;
    const int4* rowh = (const int4*)(g_uh + (size_t)bt * DUx);
    float acc = 0.f;
    #pragma unroll
    for (int c = 0; c < 2; c++){
        int idx = c*32 + lane;
        int4 h = rowh[idx];
        __half2* hp = (__half2*)&h;
        #pragma unroll
        for (int j = 0; j < 4; j++){
            float2 uv = __half22float2(hp[j]);
            float2 qv = s_qk2[idx*4 + j];
            acc += uv.x*qv.x + uv.y*qv.y;
        }
    }
    acc = warpSum(acc);
    if (lane == 0) g_base[bt] = acc * INV_SCALE + g_sbias[bt];
}

// ---------------- softmax over T: logits = (base - sp)/temp ----------------
__global__ void k_softmax1(const float* __restrict__ lt){
    int b = blockIdx.x;
    int i0 = b*TT + threadIdx.x, i1 = i0 + 1024;
    __shared__ float sh[32];
    float temp = fminf(fmaxf(expf(lt[0]), 0.1f), 10.f);
    float invT = 1.f / temp;
    float l0 = (g_base[i0] - g_sp[i0]) * invT;
    float l1 = (g_base[i1] - g_sp[i1]) * invT;
    g_logits[i0] = l0; g_logits[i1] = l1;
    float m = blockMax(fmaxf(l0, l1), sh);
    float e0 = expf(l0 - m), e1 = expf(l1 - m);
    float S = blockSum(e0 + e1, sh);
    float inv = 1.f / S;
    g_y[i0] = e0*inv; g_y[i1] = e1*inv;
}

// ---------------- stage-0 overlap: read fp32 sim, compute sim@y, emit fp16 sim ----------------
__global__ void k_simmv_conv(const float* __restrict__ sim){
    int b  = blockIdx.x >> 8;
    int t0 = (blockIdx.x & 255) * 8;
    __shared__ float4 s_y4[TT/4];
    for (int i = threadIdx.x; i < TT/4; i += blockDim.x)
        s_y4[i] = ((const float4*)(g_y + b*TT))[i];
    __syncthreads();
    int w = threadIdx.x >> 5, lane = threadIdx.x & 31;
    int t = t0 + w, bt = b*TT + t;
    const float4* row = (const float4*)(sim + (size_t)bt * TT);
    int4* out = (int4*)(g_simh + (size_t)bt * TT);
    float acc = 0.f;
    #pragma unroll
    for (int c = 0; c < 8; c++){
        int idx = c*32 + lane;
        float4 f0 = row[2*idx], f1 = row[2*idx+1];
        float4 y0 = s_y4[2*idx], y1 = s_y4[2*idx+1];
        acc += f0.x*y0.x + f0.y*y0.y + f0.z*y0.z + f0.w*y0.w
             + f1.x*y1.x + f1.y*y1.y + f1.z*y1.z + f1.w*y1.w;
        __half2 h0 = __floats2half2_rn(f0.x, f0.y);
        __half2 h1 = __floats2half2_rn(f0.z, f0.w);
        __half2 h2 = __floats2half2_rn(f1.x, f1.y);
        __half2 h3 = __floats2half2_rn(f1.z, f1.w);
        int4 o;
        o.x = *(int*)&h0; o.y = *(int*)&h1; o.z = *(int*)&h2; o.w = *(int*)&h3;
        out[idx] = o;
    }
    acc = warpSum(acc);
    if (lane == 0) g_overlap[bt] = acc;
}

// ---------------- fp16 sim matvec: overlap = sim@y  or  sp += sim@y ----------------
__global__ void k_simmv_h(int accumulate){
    int b  = blockIdx.x >> 8;
    int t0 = (blockIdx.x & 255) * 8;
    __shared__ float2 s_y2[TT/2];
    for (int i = threadIdx.x; i < TT/2; i += blockDim.x)
        s_y2[i] = ((const float2*)(g_y + b*TT))[i];
    __syncthreads();
    int w = threadIdx.x >> 5, lane = threadIdx.x & 31;
    int t = t0 + w, bt = b*TT + t;
    const int4* row = (const int4*)(g_simh + (size_t)bt * TT);
    float acc = 0.f;
    #pragma unroll
    for (int c = 0; c < 8; c++){
        int idx = c*32 + lane;
        int4 h = row[idx];
        __half2* hp = (__half2*)&h;
        #pragma unroll
        for (int j = 0; j < 4; j++){
            float2 sv = __half22float2(hp[j]);
            float2 yv = s_y2[idx*4 + j];
            acc += sv.x*yv.x + sv.y*yv.y;
        }
    }
    acc = warpSum(acc);
    if (lane == 0){
        if (accumulate) g_sp[bt] += acc;
        else            g_overlap[bt] = acc;
    }
}

// ---------------- penalty + second softmax + scalar stats ----------------
__global__ void k_penalty(){
    int b = blockIdx.x;
    int i0 = b*TT + threadIdx.x, i1 = i0 + 1024;
    __shared__ float sh[32];
    float o0 = g_overlap[i0], o1 = g_overlap[i1];
    float mo = blockMax(fmaxf(o0, o1), sh);
    mo = fmaxf(mo, EPSV);
    float invmo = 1.f / mo;
    float l0 = g_logits[i0] - o0*invmo;
    float l1 = g_logits[i1] - o1*invmo;
    float m = blockMax(fmaxf(l0, l1), sh);
    float e0 = expf(l0 - m), e1 = expf(l1 - m);
    float S = blockSum(e0 + e1, sh);
    float invS = 1.f / S;
    float y0 = e0*invS, y1 = e1*invS;
    g_y[i0] = y0; g_y[i1] = y1;
    float ysum = blockSum(y0 + y1, sh);
    float ys = fmaxf(ysum, EPSV);
    float invys = 1.f / ys;
    float yn0 = y0*invys, yn1 = y1*invys;
    float ent = blockSum(-yn0*logf(fmaxf(yn0, EPSV)) - yn1*logf(fmaxf(yn1, EPSV)), sh);
    float wsq = blockSum(y0*g_usq[i0] + y1*g_usq[i1], sh);
    if (threadIdx.x == 0){
        g_stat[b*8+0] = ys;
        g_stat[b*8+1] = ysum * (1.f/(float)TT);
        g_stat[b*8+2] = ent;
        g_stat[b*8+3] = wsq;
        g_stat[b*8+4] = 0.f;
    }
    if (threadIdx.x < DUx) g_yu[b*DUx + threadIdx.x] = 0.f;
}

// ---------------- yu = y @ u (fp16 u; partial sums + atomics) ----------------
__global__ void k_yu(){
    int b  = blockIdx.x >> 6;
    int t0 = (blockIdx.x & 63) * 32;
    __shared__ float s_y[32];
    if (threadIdx.x < 32) s_y[threadIdx.x] = g_y[b*TT + t0 + threadIdx.x];
    __syncthreads();
    float ax = 0.f, ay = 0.f;
    const __half2* up = (const __half2*)(g_uh + ((size_t)b*TT + t0) * DUx);
    #pragma unroll 8
    for (int i = 0; i < 32; i++){
        float yv = s_y[i];
        float2 v = __half22float2(up[i*256 + threadIdx.x]);
        ax += yv * v.x; ay += yv * v.y;
    }
    atomicAdd(&g_yu[b*DUx + 2*threadIdx.x],     ax);
    atomicAdd(&g_yu[b*DUx + 2*threadIdx.x + 1], ay);
}

// ---------------- spread: sum_t y_t * ||u_t - cen||  (fp16 u) ----------------
__global__ void k_dist(){
    int b  = blockIdx.x >> 8;
    int t0 = (blockIdx.x & 255) * 8;
    __shared__ float2 s_cen2[DUx/2];
    __shared__ float sh[32];
    float invys = 1.f / g_stat[b*8+0];
    for (int i = threadIdx.x; i < DUx/2; i += 256){
        float2 c2 = ((const float2*)(g_yu + b*DUx))[i];
        s_cen2[i] = make_float2(c2.x*invys, c2.y*invys);
    }
    __syncthreads();
    int w = threadIdx.x >> 5, lane = threadIdx.x & 31;
    int t = t0 + w, bt = b*TT + t;
    const int4* rowh = (const int4*)(g_uh + (size_t)bt * DUx);
    float acc = 0.f;
    #pragma unroll
    for (int c = 0; c < 2; c++){
        int idx = c*32 + lane;
        int4 h = rowh[idx];
        __half2* hp = (__half2*)&h;
        #pragma unroll
        for (int j = 0; j < 4; j++){
            float2 uv = __half22float2(hp[j]);
            float2 cn = s_cen2[idx*4 + j];
            float dx = uv.x - cn.x, dy = uv.y - cn.y;
            acc += dx*dx + dy*dy;
        }
    }
    acc = warpSum(acc);
    float part = (lane == 0) ? g_y[bt] * sqrtf(acc) : 0.f;
    float tot = blockSum(part, sh);
    if (threadIdx.x == 0) atomicAdd(&g_stat[b*8+4], tot);
}

// ---------------- z = Wv @ yu ; write out + build x = [z, c] ----------------
__global__ void k_zx(const float* __restrict__ Wv, float* __restrict__ out, int stage){
    int b = blockIdx.x >> 3;
    int c = blockIdx.x & 7;
    __shared__ float4 s_yu4[DUx/4];
    __shared__ float sh[32];
    float* s_yu = (float*)s_yu4;
    for (int i = threadIdx.x; i < DUx; i += 256) s_yu[i] = g_yu[b*DUx + i];
    __syncthreads();
    int w = threadIdx.x >> 5, lane = threadIdx.x & 31;
    #pragma unroll
    for (int j = 0; j < 8; j++){
        int d = c*64 + w*8 + j;
        const float4* row = (const float4*)(Wv + (size_t)d * DUx);
        float acc = 0.f;
        #pragma unroll
        for (int cc = 0; cc < 4; cc++){
            int idx = cc*32 + lane;
            float4 a = row[idx], yv = s_yu4[idx];
            acc += a.x*yv.x + a.y*yv.y + a.z*yv.z + a.w*yv.w;
        }
        acc = warpSum(acc);
        if (lane == 0){
            out[((size_t)b*NSTAGE + stage)*DUx + d] = acc;
            g_x[b*DXx + d] = acc;
        }
    }
    if (c == 0){
        float v0 = s_yu[threadIdx.x], v1 = s_yu[threadIdx.x + 256];
        float csq = blockSum(v0*v0 + v1*v1, sh);
        if (threadIdx.x == 0){
            float ys  = g_stat[b*8+0];
            float compact = 2.f * (ys * g_stat[b*8+3] - csq) / fmaxf(ys*ys, EPSV);
            g_x[b*DXx + 512] = g_stat[b*8+1];
            g_x[b*DXx + 513] = g_stat[b*8+2];
            g_x[b*DXx + 514] = g_stat[b*8+4] / ys;
            g_x[b*DXx + 515] = compact;
        }
    }
}

// ---------------- GRU cell update (double-buffered memory) ----------------
__global__ void k_gru(const float* __restrict__ W_ih, const float* __restrict__ b_ih,
                      const float* __restrict__ W_hh, const float* __restrict__ b_hh,
                      int inB){
    const float* mem_in  = inB ? g_memB : g_memA;
    float*       mem_out = inB ? g_memA : g_memB;
    int b = blockIdx.x >> 3;
    int c = blockIdx.x & 7;
    __shared__ float4 s_x4[DXx/4];
    __shared__ float4 s_m4[DMx/4];
    float* s_x = (float*)s_x4; float* s_m = (float*)s_m4;
    for (int i = threadIdx.x; i < DXx; i += 256) s_x[i] = g_x[b*DXx + i];
    for (int i = threadIdx.x; i < DMx; i += 256) s_m[i] = mem_in[b*DMx + i];
    __syncthreads();
    int w = threadIdx.x >> 5, lane = threadIdx.x & 31;
    for (int jj = 0; jj < 8; jj++){
        int j = c*64 + w*8 + jj;
        float gi[3], gh[3];
        #pragma unroll
        for (int g = 0; g < 3; g++){
            int r = j + g*DMx;
            const float4* wi = (const float4*)(W_ih + (size_t)r * DXx);
            float acc = 0.f;
            #pragma unroll
            for (int cc = 0; cc < 4; cc++){
                int idx = cc*32 + lane;
                float4 a = wi[idx], xx = s_x4[idx];
                acc += a.x*xx.x + a.y*xx.y + a.z*xx.z + a.w*xx.w;
            }
            if (lane == 0){
                float4 a = wi[128], xx = s_x4[128];
                acc += a.x*xx.x + a.y*xx.y + a.z*xx.z + a.w*xx.w;
            }
            acc = warpSum(acc);
            gi[g] = acc + b_ih[r];

            const float4* wh = (const float4*)(W_hh + (size_t)r * DMx);
            float acch = 0.f;
            #pragma unroll
            for (int cc = 0; cc < 4; cc++){
                int idx = cc*32 + lane;
                float4 a = wh[idx], mm = s_m4[idx];
                acch += a.x*mm.x + a.y*mm.y + a.z*mm.z + a.w*mm.w;
            }
            acch = warpSum(acch);
            gh[g] = acch + b_hh[r];
        }
        if (lane == 0){
            float rg = 1.f / (1.f + expf(-(gi[0] + gh[0])));
            float zg = 1.f / (1.f + expf(-(gi[1] + gh[1])));
            float ng = tanhf(gi[2] + rg * gh[2]);
            mem_out[b*DMx + j] = (1.f - zg) * ng + zg * s_m[j];
        }
    }
}

// ---------------- launch ----------------
extern "C" void kernel_launch(void* const* d_in, const int* in_sizes, int n_in,
                              void* d_out, int out_size){
    const float* u    = (const float*)d_in[0];
    const float* sf   = (const float*)d_in[1];
    const float* sim  = (const float*)d_in[2];
    const float* mem0 = (const float*)d_in[3];
    const float* Wq   = (const float*)d_in[4];
    const float* Wk   = (const float*)d_in[5];
    const float* Wv   = (const float*)d_in[6];
    const float* sbw1 = (const float*)d_in[7];
    const float* sbb1 = (const float*)d_in[8];
    const float* sbw2 = (const float*)d_in[9];
    const float* sbb2 = (const float*)d_in[10];
    const float* lt   = (const float*)d_in[11];
    const float* Wih  = (const float*)d_in[12];
    const float* bih  = (const float*)d_in[13];
    const float* Whh  = (const float*)d_in[14];
    const float* bhh  = (const float*)d_in[15];
    float* out = (float*)d_out;

    // one-time stream/event creation (happens on the first, non-captured call;
    // identical launched work every call)
    static cudaStream_t s2 = nullptr;
    static cudaEvent_t evF[3], evJ[3];
    if (s2 == nullptr){
        cudaStreamCreateWithFlags(&s2, cudaStreamNonBlocking);
        for (int i = 0; i < 3; i++){
            cudaEventCreateWithFlags(&evF[i], cudaEventDisableTiming);
            cudaEventCreateWithFlags(&evJ[i], cudaEventDisableTiming);
        }
    }

    k_init<<<64, 256>>>(mem0);
    k_Mpre<<<256, 256>>>(Wk, Wq);
    k_pre<<<BB*TT/8, 256>>>(u, sf, sbw1, sbb1, sbw2, sbb2);

    for (int s = 0; s < NSTAGE; s++){
        int inB = s & 1;
        k_qk<<<BB*16, 256>>>(inB);
        k_scores<<<BB*TT/8, 256>>>();
        if (s > 0) cudaStreamWaitEvent(0, evJ[s-1], 0);   // sp update complete
        k_softmax1<<<BB, 1024>>>(lt);
        if (s == 0)
            k_simmv_conv<<<BB*TT/8, 256>>>(sim);          // overlap + fp16 compress
        else
            k_simmv_h<<<BB*TT/8, 256>>>(0);               // overlap = sim @ y_pre
        k_penalty<<<BB, 1024>>>();                        // y_final + scalar stats
        if (s < NSTAGE - 1){
            // fork: sp += sim @ y_final on side stream, hidden behind stats/GRU chain
            cudaEventRecord(evF[s], 0);
            cudaStreamWaitEvent(s2, evF[s], 0);
            k_simmv_h<<<BB*TT/8, 256, 0, s2>>>(1);
            cudaEventRecord(evJ[s], s2);
        }
        k_yu<<<BB*64, 256>>>();
        k_dist<<<BB*TT/8, 256>>>();
        k_zx<<<BB*8, 256>>>(Wv, out, s);
        k_gru<<<BB*8, 256>>>(Wih, bih, Whh, bhh, inB);
    }
}